// round 11
// baseline (speedup 1.0000x reference)
#include <cuda_runtime.h>

// Magnus2: x_{n+1} = E_n x_n, 2x2 time-dependent, batch-independent E.
// SINGLE fused kernel, 1024 blocks x 256 threads, all resident (8 CTA/SM):
//   blocks 0..63: compute E + block-local (128-slot) fp32 scan -> g_L, g_agg;
//                 last-finishing block: fp64 prefix scan -> g_pref, release flag
//   all blocks:   spin on flag (tid 0 + backoff), then stream y = P @ x0
// Flag/counters are reset in-kernel once every block has passed the spin,
// so every graph replay starts from identical state.

#define MAX_T   8192
#define SPB     128                 // slots per scan block
#define MAX_NB  (MAX_T / SPB)       // 64
#define NCHUNK  32                  // n-rows per block

__device__ float4   g_L[MAX_T];     // block-local inclusive products
__device__ float4   g_agg[MAX_NB];  // per-scan-block aggregates
__device__ float4   g_pref[MAX_NB]; // exclusive prefixes (g_pref[0] = I)
__device__ unsigned g_scan_done;    // # scan blocks finished
__device__ unsigned g_flag;         // prefixes published
__device__ unsigned g_post;         // # blocks past the spin

// fp32 2x2 multiply: R = X @ Y  (x=00 y=01 z=10 w=11)
__device__ __forceinline__ float4 mmul32(float4 X, float4 Y) {
    float4 r;
    r.x = X.x * Y.x + X.y * Y.z;
    r.y = X.x * Y.y + X.y * Y.w;
    r.z = X.z * Y.x + X.w * Y.z;
    r.w = X.z * Y.y + X.w * Y.w;
    return r;
}

struct M2d { double a, b, c, d; };
__device__ __forceinline__ M2d mmul64(const M2d& X, const M2d& Y) {
    M2d r;
    r.a = X.a * Y.a + X.b * Y.c;
    r.b = X.a * Y.b + X.b * Y.d;
    r.c = X.c * Y.a + X.d * Y.c;
    r.d = X.c * Y.b + X.d * Y.d;
    return r;
}
__device__ __forceinline__ M2d toD(float4 v) {
    return { (double)v.x, (double)v.y, (double)v.z, (double)v.w };
}
__device__ __forceinline__ float4 toF(const M2d& v) {
    return make_float4((float)v.a, (float)v.b, (float)v.c, (float)v.d);
}

__device__ __forceinline__ float4 shflup4(float4 v, int off) {
    float4 r;
    r.x = __shfl_up_sync(0xFFFFFFFFu, v.x, off);
    r.y = __shfl_up_sync(0xFFFFFFFFu, v.y, off);
    r.z = __shfl_up_sync(0xFFFFFFFFu, v.z, off);
    r.w = __shfl_up_sync(0xFFFFFFFFu, v.w, off);
    return r;
}
__device__ __forceinline__ M2d shflupD(const M2d& v, int off) {
    M2d r;
    r.a = __shfl_up_sync(0xFFFFFFFFu, v.a, off);
    r.b = __shfl_up_sync(0xFFFFFFFFu, v.b, off);
    r.c = __shfl_up_sync(0xFFFFFFFFu, v.c, off);
    r.d = __shfl_up_sync(0xFFFFFFFFu, v.d, off);
    return r;
}

// sin(x) for |x| up to ~1e3: Cody-Waite 2-term reduction + MUFU sin.
__device__ __forceinline__ float fast_sin(float x) {
    float k = rintf(x * 0.15915494309189535f);
    float r = fmaf(k, -6.2831855f, x);
    r = fmaf(k, 1.7484555e-7f, r);
    return __sinf(r);
}

// ---------------------------------------------------------------------------
__global__ void __launch_bounds__(256, 8)
fused_kernel(const float* __restrict__ t,
             const float* __restrict__ p_w,
             const float* __restrict__ p_g0,
             const float* __restrict__ p_ga,
             const float* __restrict__ p_wd,
             const int*   __restrict__ p_uc,
             const float* __restrict__ x0,
             float* __restrict__ out,
             int B, int T)
{
    __shared__ float4 sWA[4], sWP[4];
    __shared__ float4 sP[NCHUNK];
    __shared__ int sLast;

    const int tid  = threadIdx.x;
    const int bx   = blockIdx.x;
    const int lane = tid & 31;
    const int wid  = tid >> 5;
    const int NBs  = (T + SPB - 1) / SPB;     // 64

    // ------------------- Phase A: scan (blocks 0..NBs-1) -------------------
    if (bx < NBs) {
        float4 agg = make_float4(1.0f, 0.0f, 0.0f, 1.0f);
        const int s = bx * SPB + tid;

        if (wid < 4) {   // threads 0..127 carry the 128 slots
            if (s >= 1 && s < T) {
                const float w  = *p_w;
                const float g0 = *p_g0;
                const float ga = *p_ga;
                const float wd = *p_wd;
                const int   uc = *p_uc;

                const int i = s - 1;
                const float t0 = t[i];
                const float t1 = t[i + 1];
                const float dt = t1 - t0;
                const float tm = t0 + dt * 0.5f;
                const float gm = g0 * (1.0f + ga * fast_sin(wd * tm));

                float O00 = 0.0f;
                float O01 = dt;
                float O10 = -w * dt;
                float O11 = -gm * dt;
                if (uc) {
                    const float gA = g0 * (1.0f + ga * fast_sin(wd * t0));
                    const float gB = g0 * (1.0f + ga * fast_sin(wd * t1));
                    const float dg = gA - gB;
                    const float c  = dt * dt * (1.0f / 12.0f);
                    O01 += c * dg;
                    O10 += c * w * dg;
                }

                const float m     = 0.5f * (O00 + O11);
                const float det   = O00 * O11 - O01 * O10;
                const float delta = m * m - det;

                float cosl, sinch;
                if (fabsf(delta) < 0.01f) {
                    cosl  = 1.0f + delta * (0.5f + delta * (1.0f / 24.0f));
                    sinch = 1.0f + delta * ((1.0f / 6.0f) + delta * (1.0f / 120.0f));
                } else {
                    const float sq    = sqrtf(fabsf(delta));
                    const bool  pos   = (delta >= 0.0f);
                    const bool  smll  = (sq < 1e-6f);
                    const float ssafe = smll ? 1.0f : sq;
                    cosl  = pos ? coshf(sq) : cosf(sq);
                    sinch = smll ? 1.0f : ((pos ? sinhf(ssafe) : sinf(ssafe)) / ssafe);
                }
                const float em = __expf(m);

                agg.x = em * (cosl + sinch * (O00 - m));
                agg.y = em * (sinch * O01);
                agg.z = em * (sinch * O10);
                agg.w = em * (cosl + sinch * (O11 - m));
            }
            // warp inclusive scan (combine: newer @ older; adjacent segments)
            #pragma unroll
            for (int off = 1; off < 32; off <<= 1) {
                float4 prev = shflup4(agg, off);
                if (lane >= off) agg = mmul32(agg, prev);
            }
            if (lane == 31) sWA[wid] = agg;
        }
        __syncthreads();
        if (tid == 0) {
            float4 p = make_float4(1.0f, 0.0f, 0.0f, 1.0f);
            #pragma unroll
            for (int wi = 0; wi < 4; wi++) { sWP[wi] = p; p = mmul32(sWA[wi], p); }
        }
        __syncthreads();
        if (wid < 4) {
            if (wid > 0) agg = mmul32(agg, sWP[wid]);
            if (s < T) g_L[s] = agg;
            if (tid == SPB - 1) g_agg[bx] = agg;
            __threadfence();              // release this thread's stores
        }
        __syncthreads();
        if (tid == 0) {
            unsigned old = atomicAdd(&g_scan_done, 1u);
            sLast = (old == (unsigned)(NBs - 1)) ? 1 : 0;
        }
        __syncthreads();

        if (sLast && wid == 0) {
            __threadfence();              // acquire all g_agg
            const int i0 = 2 * lane, i1 = 2 * lane + 1;
            const M2d I = {1.0, 0.0, 0.0, 1.0};
            M2d a0 = (i0 < NBs) ? toD(g_agg[i0]) : I;
            M2d a1 = (i1 < NBs) ? toD(g_agg[i1]) : I;
            M2d p  = mmul64(a1, a0);      // ordered newer @ older
            #pragma unroll
            for (int off = 1; off < 32; off <<= 1) {
                M2d prev = shflupD(p, off);
                if (lane >= off) p = mmul64(p, prev);
            }
            M2d Sm1 = shflupD(p, 1);
            M2d pref0 = (lane == 0) ? I : Sm1;
            M2d pref1 = mmul64(a0, pref0);
            if (i0 < MAX_NB) g_pref[i0] = toF(pref0);
            if (i1 < MAX_NB) g_pref[i1] = toF(pref1);
            __threadfence();              // release g_pref (per lane)
            __syncwarp();
            if (lane == 0) atomicExch(&g_flag, 1u);
        }
    }

    // ------------------- Phase B: output (all blocks) -------------------
    const int B4 = B >> 2;
    const int nx = B4 >> 8;               // # 256-wide b4 tiles (4 for B=4096)
    const int b4 = (bx % nx) * 256 + tid;
    const int n0 = (bx / nx) * NCHUNK;

    // preload x0 before the spin (overlaps scan phase)
    const float4 a0 = ((const float4*)x0)[b4];
    const float4 a1 = ((const float4*)(x0 + B))[b4];

    if (tid == 0) {
        while (*(volatile unsigned*)&g_flag == 0u) __nanosleep(128);
        unsigned old = atomicAdd(&g_post, 1u);
        if (old == (unsigned)gridDim.x - 1u) {
            // every block has passed the spin: reset state for the next replay
            g_flag = 0u; g_scan_done = 0u; g_post = 0u;
        }
    }
    __syncthreads();                      // all threads see flag passed

    if (tid < NCHUNK) {
        int nn = n0 + tid;
        if (nn >= T) nn = T - 1;
        sP[tid] = mmul32(g_L[nn], g_pref[n0 / SPB]);   // g_pref[0] == I
    }
    __syncthreads();

    if (b4 >= B4) return;

    float4* o = (float4*)out + (size_t)n0 * 2 * B4 + b4;

    #pragma unroll 4
    for (int j = 0; j < NCHUNK; j++) {
        const int n = n0 + j;
        if (n >= T) break;
        const float4 P = sP[j];

        float4 y0, y1;
        y0.x = P.x * a0.x + P.y * a1.x;
        y0.y = P.x * a0.y + P.y * a1.y;
        y0.z = P.x * a0.z + P.y * a1.z;
        y0.w = P.x * a0.w + P.y * a1.w;
        y1.x = P.z * a0.x + P.w * a1.x;
        y1.y = P.z * a0.y + P.w * a1.y;
        y1.z = P.z * a0.z + P.w * a1.z;
        y1.w = P.z * a0.w + P.w * a1.w;

        __stcs(o, y0);
        __stcs(o + B4, y1);
        o += 2 * B4;
    }
}

// ---------------------------------------------------------------------------
extern "C" void kernel_launch(void* const* d_in, const int* in_sizes, int n_in,
                              void* d_out, int out_size)
{
    const float* t  = (const float*)d_in[0];
    const float* x0 = (const float*)d_in[1];
    const float* w  = (const float*)d_in[2];
    const float* g0 = (const float*)d_in[3];
    const float* ga = (const float*)d_in[4];
    const float* wd = (const float*)d_in[5];
    const int*   uc = (const int*)d_in[6];
    float* out = (float*)d_out;

    const int T  = in_sizes[0];        // 8192
    const int B  = in_sizes[1] / 2;    // 4096
    const int B4 = B >> 2;
    const int nx = B4 / 256;           // 4
    const int ny = (T + NCHUNK - 1) / NCHUNK;   // 256
    const int blocks = nx * ny;        // 1024 (>= 64 scan blocks; all resident)

    fused_kernel<<<blocks, 256>>>(t, w, g0, ga, wd, uc, x0, out, B, T);
}

// round 14
// speedup vs baseline: 1.0908x; 1.0908x over previous
#include <cuda_runtime.h>

// Magnus2: x_{n+1} = E_n x_n, 2x2 time-dependent, batch-independent E.
//   K1: compute E + block-local (128-slot) fp32 scan; last-finishing block
//       computes all 64 exclusive block prefixes (fp64 warp scan) -> g_pref
//   K3: stage P[n] = L[n] @ pref (one mmul32) then stream y = P @ x0.
// This is the measured-optimal configuration (49.2us): total time sits on the
// DRAM write-drain floor (268 MB / ~5.45 TB/s); all structural variants
// (PDL, fusion, occupancy caps, unrolling) measured neutral or worse.

#define MAX_T   8192
#define SPB     128                 // slots per scan block
#define MAX_NB  (MAX_T / SPB)       // 64
#define NCHUNK  32                  // n-rows per out-block (1024 blocks -> 1 full wave)

__device__ float4   g_L[MAX_T];     // block-local inclusive products
__device__ float4   g_agg[MAX_NB];  // per-scan-block aggregates
__device__ float4   g_pref[MAX_NB]; // exclusive prefixes (g_pref[0] = I)
__device__ unsigned g_count;        // monotonic; (old+1) % gridDim.x == 0 -> last block

// fp32 2x2 multiply: R = X @ Y  (x=00 y=01 z=10 w=11)
__device__ __forceinline__ float4 mmul32(float4 X, float4 Y) {
    float4 r;
    r.x = X.x * Y.x + X.y * Y.z;
    r.y = X.x * Y.y + X.y * Y.w;
    r.z = X.z * Y.x + X.w * Y.z;
    r.w = X.z * Y.y + X.w * Y.w;
    return r;
}

struct M2d { double a, b, c, d; };
__device__ __forceinline__ M2d mmul64(const M2d& X, const M2d& Y) {
    M2d r;
    r.a = X.a * Y.a + X.b * Y.c;
    r.b = X.a * Y.b + X.b * Y.d;
    r.c = X.c * Y.a + X.d * Y.c;
    r.d = X.c * Y.b + X.d * Y.d;
    return r;
}
__device__ __forceinline__ M2d toD(float4 v) {
    return { (double)v.x, (double)v.y, (double)v.z, (double)v.w };
}
__device__ __forceinline__ float4 toF(const M2d& v) {
    return make_float4((float)v.a, (float)v.b, (float)v.c, (float)v.d);
}

__device__ __forceinline__ float4 shflup4(float4 v, int off) {
    float4 r;
    r.x = __shfl_up_sync(0xFFFFFFFFu, v.x, off);
    r.y = __shfl_up_sync(0xFFFFFFFFu, v.y, off);
    r.z = __shfl_up_sync(0xFFFFFFFFu, v.z, off);
    r.w = __shfl_up_sync(0xFFFFFFFFu, v.w, off);
    return r;
}
__device__ __forceinline__ M2d shflupD(const M2d& v, int off) {
    M2d r;
    r.a = __shfl_up_sync(0xFFFFFFFFu, v.a, off);
    r.b = __shfl_up_sync(0xFFFFFFFFu, v.b, off);
    r.c = __shfl_up_sync(0xFFFFFFFFu, v.c, off);
    r.d = __shfl_up_sync(0xFFFFFFFFu, v.d, off);
    return r;
}

// sin(x) for |x| up to ~1e3: Cody-Waite 2-term reduction + MUFU sin.
__device__ __forceinline__ float fast_sin(float x) {
    float k = rintf(x * 0.15915494309189535f);
    float r = fmaf(k, -6.2831855f, x);
    r = fmaf(k, 1.7484555e-7f, r);
    return __sinf(r);
}

// ---------------------------------------------------------------------------
// K1
// ---------------------------------------------------------------------------
__global__ void __launch_bounds__(SPB)
k1_E_scan(const float* __restrict__ t,
          const float* __restrict__ p_w,
          const float* __restrict__ p_g0,
          const float* __restrict__ p_ga,
          const float* __restrict__ p_wd,
          const int*   __restrict__ p_uc,
          int T)
{
    __shared__ float4 sWA[4], sWP[4];
    __shared__ int sLast;
    const int tid  = threadIdx.x;
    const int lane = tid & 31;
    const int wid  = tid >> 5;
    const int s    = blockIdx.x * SPB + tid;

    float4 E = make_float4(1.0f, 0.0f, 0.0f, 1.0f);
    if (s >= 1 && s < T) {
        const float w  = *p_w;
        const float g0 = *p_g0;
        const float ga = *p_ga;
        const float wd = *p_wd;
        const int   uc = *p_uc;

        const int i = s - 1;
        const float t0 = t[i];
        const float t1 = t[i + 1];
        const float dt = t1 - t0;
        const float tm = t0 + dt * 0.5f;
        const float gm = g0 * (1.0f + ga * fast_sin(wd * tm));

        float O00 = 0.0f;
        float O01 = dt;
        float O10 = -w * dt;
        float O11 = -gm * dt;
        if (uc) {
            const float gA = g0 * (1.0f + ga * fast_sin(wd * t0));
            const float gB = g0 * (1.0f + ga * fast_sin(wd * t1));
            const float dg = gA - gB;
            const float c  = dt * dt * (1.0f / 12.0f);
            O01 += c * dg;
            O10 += c * w * dg;
        }

        const float m     = 0.5f * (O00 + O11);
        const float det   = O00 * O11 - O01 * O10;
        const float delta = m * m - det;

        float cosl, sinch;
        if (fabsf(delta) < 0.01f) {
            cosl  = 1.0f + delta * (0.5f + delta * (1.0f / 24.0f));
            sinch = 1.0f + delta * ((1.0f / 6.0f) + delta * (1.0f / 120.0f));
        } else {
            const float sq    = sqrtf(fabsf(delta));
            const bool  pos   = (delta >= 0.0f);
            const bool  smll  = (sq < 1e-6f);
            const float ssafe = smll ? 1.0f : sq;
            cosl  = pos ? coshf(sq) : cosf(sq);
            sinch = smll ? 1.0f : ((pos ? sinhf(ssafe) : sinf(ssafe)) / ssafe);
        }
        const float em = __expf(m);

        E.x = em * (cosl + sinch * (O00 - m));
        E.y = em * (sinch * O01);
        E.z = em * (sinch * O10);
        E.w = em * (cosl + sinch * (O11 - m));
    }

    // warp-level inclusive scan (combine: newer @ older; adjacent segments)
    float4 agg = E;
    #pragma unroll
    for (int off = 1; off < 32; off <<= 1) {
        float4 prev = shflup4(agg, off);
        if (lane >= off) agg = mmul32(agg, prev);
    }
    if (lane == 31) sWA[wid] = agg;
    __syncthreads();
    if (tid == 0) {
        float4 p = make_float4(1.0f, 0.0f, 0.0f, 1.0f);
        #pragma unroll
        for (int wi = 0; wi < 4; wi++) { sWP[wi] = p; p = mmul32(sWA[wi], p); }
    }
    __syncthreads();
    if (wid > 0) agg = mmul32(agg, sWP[wid]);

    if (s < T) g_L[s] = agg;

    // publish aggregate; detect last-finishing block (monotonic, replay-safe)
    if (tid == SPB - 1) {
        g_agg[blockIdx.x] = agg;
        __threadfence();
        unsigned old = atomicAdd(&g_count, 1u);
        sLast = (((old + 1) % gridDim.x) == 0) ? 1 : 0;
    }
    __syncthreads();

    // last block: one-warp fp64 scan over NB aggregates -> exclusive prefixes
    if (sLast && wid == 0) {
        __threadfence();
        const int NB = gridDim.x;      // 64 for T=8192
        const int i0 = 2 * lane, i1 = 2 * lane + 1;
        const M2d I = {1.0, 0.0, 0.0, 1.0};
        M2d a0 = (i0 < NB) ? toD(g_agg[i0]) : I;
        M2d a1 = (i1 < NB) ? toD(g_agg[i1]) : I;
        M2d p  = mmul64(a1, a0);       // pair product, ordered newer@older
        #pragma unroll
        for (int off = 1; off < 32; off <<= 1) {
            M2d prev = shflupD(p, off);
            if (lane >= off) p = mmul64(p, prev);
        }
        M2d Sm1 = shflupD(p, 1);
        M2d pref0 = (lane == 0) ? I : Sm1;
        M2d pref1 = mmul64(a0, pref0);
        if (i0 < MAX_NB) g_pref[i0] = toF(pref0);
        if (i1 < MAX_NB) g_pref[i1] = toF(pref1);
    }
}

// ---------------------------------------------------------------------------
// K3: stage P for NCHUNK rows (one mmul32 fixup), then stream y = P @ x0.
// Proven loop shape: #pragma unroll 4, running pointer, per-iter guard.
// ---------------------------------------------------------------------------
__global__ void __launch_bounds__(256)
k3_out(const float* __restrict__ x0,
       float* __restrict__ out,
       int B, int T)
{
    __shared__ float4 sP[NCHUNK];
    const int tid = threadIdx.x;
    const int B4  = B >> 2;
    const int b4  = blockIdx.x * 256 + tid;
    const int n0  = blockIdx.y * NCHUNK;

    if (tid < NCHUNK) {
        int nn = n0 + tid;
        if (nn >= T) nn = T - 1;
        float4 L  = g_L[nn];
        float4 pr = g_pref[n0 >> 7];   // SPB == 128; constant over the chunk
        sP[tid] = mmul32(L, pr);       // g_pref[0] == I
    }
    __syncthreads();

    if (b4 >= B4) return;

    const float4 a0 = ((const float4*)x0)[b4];
    const float4 a1 = ((const float4*)(x0 + B))[b4];

    float4* o = (float4*)out + (size_t)n0 * 2 * B4 + b4;

    #pragma unroll 4
    for (int j = 0; j < NCHUNK; j++) {
        const int n = n0 + j;
        if (n >= T) break;
        const float4 P = sP[j];

        float4 y0, y1;
        y0.x = P.x * a0.x + P.y * a1.x;
        y0.y = P.x * a0.y + P.y * a1.y;
        y0.z = P.x * a0.z + P.y * a1.z;
        y0.w = P.x * a0.w + P.y * a1.w;
        y1.x = P.z * a0.x + P.w * a1.x;
        y1.y = P.z * a0.y + P.w * a1.y;
        y1.z = P.z * a0.z + P.w * a1.z;
        y1.w = P.z * a0.w + P.w * a1.w;

        __stcs(o, y0);
        __stcs(o + B4, y1);
        o += 2 * B4;
    }
}

// ---------------------------------------------------------------------------
extern "C" void kernel_launch(void* const* d_in, const int* in_sizes, int n_in,
                              void* d_out, int out_size)
{
    const float* t  = (const float*)d_in[0];
    const float* x0 = (const float*)d_in[1];
    const float* w  = (const float*)d_in[2];
    const float* g0 = (const float*)d_in[3];
    const float* ga = (const float*)d_in[4];
    const float* wd = (const float*)d_in[5];
    const int*   uc = (const int*)d_in[6];
    float* out = (float*)d_out;

    const int T = in_sizes[0];       // 8192
    const int B = in_sizes[1] / 2;   // 4096
    const int NB = (T + SPB - 1) / SPB;   // 64

    k1_E_scan<<<NB, SPB>>>(t, w, g0, ga, wd, uc, T);

    {
        const int B4 = B >> 2;
        dim3 grid((B4 + 255) / 256, (T + NCHUNK - 1) / NCHUNK);
        k3_out<<<grid, 256>>>(x0, out, B, T);
    }
}

// round 15
// speedup vs baseline: 1.1384x; 1.0437x over previous
#include <cuda_runtime.h>

// Magnus2: x_{n+1} = E_n x_n, 2x2 time-dependent, batch-independent E.
//   K1: compute E + block-local (128-slot) fp32 scan; last-finishing block
//       computes all 64 exclusive block prefixes (fp64 warp scan) -> g_pref
//   K3: stage P[n] = L[n] @ pref (one mmul32) then stream y = P @ x0.
// Experiment: NCHUNK=16 -> 2048 out-blocks (2 waves) to probe the store
// concurrency curve above the 1024-block point.

#define MAX_T   8192
#define SPB     128                 // slots per scan block
#define MAX_NB  (MAX_T / SPB)       // 64
#define NCHUNK  16                  // n-rows per out-block (2048 blocks)

__device__ float4   g_L[MAX_T];     // block-local inclusive products
__device__ float4   g_agg[MAX_NB];  // per-scan-block aggregates
__device__ float4   g_pref[MAX_NB]; // exclusive prefixes (g_pref[0] = I)
__device__ unsigned g_count;        // monotonic; (old+1) % gridDim.x == 0 -> last block

// fp32 2x2 multiply: R = X @ Y  (x=00 y=01 z=10 w=11)
__device__ __forceinline__ float4 mmul32(float4 X, float4 Y) {
    float4 r;
    r.x = X.x * Y.x + X.y * Y.z;
    r.y = X.x * Y.y + X.y * Y.w;
    r.z = X.z * Y.x + X.w * Y.z;
    r.w = X.z * Y.y + X.w * Y.w;
    return r;
}

struct M2d { double a, b, c, d; };
__device__ __forceinline__ M2d mmul64(const M2d& X, const M2d& Y) {
    M2d r;
    r.a = X.a * Y.a + X.b * Y.c;
    r.b = X.a * Y.b + X.b * Y.d;
    r.c = X.c * Y.a + X.d * Y.c;
    r.d = X.c * Y.b + X.d * Y.d;
    return r;
}
__device__ __forceinline__ M2d toD(float4 v) {
    return { (double)v.x, (double)v.y, (double)v.z, (double)v.w };
}
__device__ __forceinline__ float4 toF(const M2d& v) {
    return make_float4((float)v.a, (float)v.b, (float)v.c, (float)v.d);
}

__device__ __forceinline__ float4 shflup4(float4 v, int off) {
    float4 r;
    r.x = __shfl_up_sync(0xFFFFFFFFu, v.x, off);
    r.y = __shfl_up_sync(0xFFFFFFFFu, v.y, off);
    r.z = __shfl_up_sync(0xFFFFFFFFu, v.z, off);
    r.w = __shfl_up_sync(0xFFFFFFFFu, v.w, off);
    return r;
}
__device__ __forceinline__ M2d shflupD(const M2d& v, int off) {
    M2d r;
    r.a = __shfl_up_sync(0xFFFFFFFFu, v.a, off);
    r.b = __shfl_up_sync(0xFFFFFFFFu, v.b, off);
    r.c = __shfl_up_sync(0xFFFFFFFFu, v.c, off);
    r.d = __shfl_up_sync(0xFFFFFFFFu, v.d, off);
    return r;
}

// sin(x) for |x| up to ~1e3: Cody-Waite 2-term reduction + MUFU sin.
__device__ __forceinline__ float fast_sin(float x) {
    float k = rintf(x * 0.15915494309189535f);
    float r = fmaf(k, -6.2831855f, x);
    r = fmaf(k, 1.7484555e-7f, r);
    return __sinf(r);
}

// ---------------------------------------------------------------------------
// K1
// ---------------------------------------------------------------------------
__global__ void __launch_bounds__(SPB)
k1_E_scan(const float* __restrict__ t,
          const float* __restrict__ p_w,
          const float* __restrict__ p_g0,
          const float* __restrict__ p_ga,
          const float* __restrict__ p_wd,
          const int*   __restrict__ p_uc,
          int T)
{
    __shared__ float4 sWA[4], sWP[4];
    __shared__ int sLast;
    const int tid  = threadIdx.x;
    const int lane = tid & 31;
    const int wid  = tid >> 5;
    const int s    = blockIdx.x * SPB + tid;

    float4 E = make_float4(1.0f, 0.0f, 0.0f, 1.0f);
    if (s >= 1 && s < T) {
        const float w  = *p_w;
        const float g0 = *p_g0;
        const float ga = *p_ga;
        const float wd = *p_wd;
        const int   uc = *p_uc;

        const int i = s - 1;
        const float t0 = t[i];
        const float t1 = t[i + 1];
        const float dt = t1 - t0;
        const float tm = t0 + dt * 0.5f;
        const float gm = g0 * (1.0f + ga * fast_sin(wd * tm));

        float O00 = 0.0f;
        float O01 = dt;
        float O10 = -w * dt;
        float O11 = -gm * dt;
        if (uc) {
            const float gA = g0 * (1.0f + ga * fast_sin(wd * t0));
            const float gB = g0 * (1.0f + ga * fast_sin(wd * t1));
            const float dg = gA - gB;
            const float c  = dt * dt * (1.0f / 12.0f);
            O01 += c * dg;
            O10 += c * w * dg;
        }

        const float m     = 0.5f * (O00 + O11);
        const float det   = O00 * O11 - O01 * O10;
        const float delta = m * m - det;

        float cosl, sinch;
        if (fabsf(delta) < 0.01f) {
            cosl  = 1.0f + delta * (0.5f + delta * (1.0f / 24.0f));
            sinch = 1.0f + delta * ((1.0f / 6.0f) + delta * (1.0f / 120.0f));
        } else {
            const float sq    = sqrtf(fabsf(delta));
            const bool  pos   = (delta >= 0.0f);
            const bool  smll  = (sq < 1e-6f);
            const float ssafe = smll ? 1.0f : sq;
            cosl  = pos ? coshf(sq) : cosf(sq);
            sinch = smll ? 1.0f : ((pos ? sinhf(ssafe) : sinf(ssafe)) / ssafe);
        }
        const float em = __expf(m);

        E.x = em * (cosl + sinch * (O00 - m));
        E.y = em * (sinch * O01);
        E.z = em * (sinch * O10);
        E.w = em * (cosl + sinch * (O11 - m));
    }

    // warp-level inclusive scan (combine: newer @ older; adjacent segments)
    float4 agg = E;
    #pragma unroll
    for (int off = 1; off < 32; off <<= 1) {
        float4 prev = shflup4(agg, off);
        if (lane >= off) agg = mmul32(agg, prev);
    }
    if (lane == 31) sWA[wid] = agg;
    __syncthreads();
    if (tid == 0) {
        float4 p = make_float4(1.0f, 0.0f, 0.0f, 1.0f);
        #pragma unroll
        for (int wi = 0; wi < 4; wi++) { sWP[wi] = p; p = mmul32(sWA[wi], p); }
    }
    __syncthreads();
    if (wid > 0) agg = mmul32(agg, sWP[wid]);

    if (s < T) g_L[s] = agg;

    // publish aggregate; detect last-finishing block (monotonic, replay-safe)
    if (tid == SPB - 1) {
        g_agg[blockIdx.x] = agg;
        __threadfence();
        unsigned old = atomicAdd(&g_count, 1u);
        sLast = (((old + 1) % gridDim.x) == 0) ? 1 : 0;
    }
    __syncthreads();

    // last block: one-warp fp64 scan over NB aggregates -> exclusive prefixes
    if (sLast && wid == 0) {
        __threadfence();
        const int NB = gridDim.x;      // 64 for T=8192
        const int i0 = 2 * lane, i1 = 2 * lane + 1;
        const M2d I = {1.0, 0.0, 0.0, 1.0};
        M2d a0 = (i0 < NB) ? toD(g_agg[i0]) : I;
        M2d a1 = (i1 < NB) ? toD(g_agg[i1]) : I;
        M2d p  = mmul64(a1, a0);       // pair product, ordered newer@older
        #pragma unroll
        for (int off = 1; off < 32; off <<= 1) {
            M2d prev = shflupD(p, off);
            if (lane >= off) p = mmul64(p, prev);
        }
        M2d Sm1 = shflupD(p, 1);
        M2d pref0 = (lane == 0) ? I : Sm1;
        M2d pref1 = mmul64(a0, pref0);
        if (i0 < MAX_NB) g_pref[i0] = toF(pref0);
        if (i1 < MAX_NB) g_pref[i1] = toF(pref1);
    }
}

// ---------------------------------------------------------------------------
// K3: stage P for NCHUNK rows (one mmul32 fixup), then stream y = P @ x0.
// Proven loop shape: #pragma unroll 4, running pointer, per-iter guard.
// ---------------------------------------------------------------------------
__global__ void __launch_bounds__(256)
k3_out(const float* __restrict__ x0,
       float* __restrict__ out,
       int B, int T)
{
    __shared__ float4 sP[NCHUNK];
    const int tid = threadIdx.x;
    const int B4  = B >> 2;
    const int b4  = blockIdx.x * 256 + tid;
    const int n0  = blockIdx.y * NCHUNK;

    if (tid < NCHUNK) {
        int nn = n0 + tid;
        if (nn >= T) nn = T - 1;
        float4 L  = g_L[nn];
        float4 pr = g_pref[n0 >> 7];   // SPB == 128; constant over the chunk
        sP[tid] = mmul32(L, pr);       // g_pref[0] == I
    }
    __syncthreads();

    if (b4 >= B4) return;

    const float4 a0 = ((const float4*)x0)[b4];
    const float4 a1 = ((const float4*)(x0 + B))[b4];

    float4* o = (float4*)out + (size_t)n0 * 2 * B4 + b4;

    #pragma unroll 4
    for (int j = 0; j < NCHUNK; j++) {
        const int n = n0 + j;
        if (n >= T) break;
        const float4 P = sP[j];

        float4 y0, y1;
        y0.x = P.x * a0.x + P.y * a1.x;
        y0.y = P.x * a0.y + P.y * a1.y;
        y0.z = P.x * a0.z + P.y * a1.z;
        y0.w = P.x * a0.w + P.y * a1.w;
        y1.x = P.z * a0.x + P.w * a1.x;
        y1.y = P.z * a0.y + P.w * a1.y;
        y1.z = P.z * a0.z + P.w * a1.z;
        y1.w = P.z * a0.w + P.w * a1.w;

        __stcs(o, y0);
        __stcs(o + B4, y1);
        o += 2 * B4;
    }
}

// ---------------------------------------------------------------------------
extern "C" void kernel_launch(void* const* d_in, const int* in_sizes, int n_in,
                              void* d_out, int out_size)
{
    const float* t  = (const float*)d_in[0];
    const float* x0 = (const float*)d_in[1];
    const float* w  = (const float*)d_in[2];
    const float* g0 = (const float*)d_in[3];
    const float* ga = (const float*)d_in[4];
    const float* wd = (const float*)d_in[5];
    const int*   uc = (const int*)d_in[6];
    float* out = (float*)d_out;

    const int T = in_sizes[0];       // 8192
    const int B = in_sizes[1] / 2;   // 4096
    const int NB = (T + SPB - 1) / SPB;   // 64

    k1_E_scan<<<NB, SPB>>>(t, w, g0, ga, wd, uc, T);

    {
        const int B4 = B >> 2;
        dim3 grid((B4 + 255) / 256, (T + NCHUNK - 1) / NCHUNK);
        k3_out<<<grid, 256>>>(x0, out, B, T);
    }
}

// round 16
// speedup vs baseline: 1.1571x; 1.0164x over previous
#include <cuda_runtime.h>

// Magnus2: x_{n+1} = E_n x_n, 2x2 time-dependent, batch-independent E.
//   K1: compute E + block-local (128-slot) fp32 scan; last-finishing block
//       computes all 64 exclusive block prefixes (fp64 warp scan) -> g_pref
//   K3: stage P[n] = L[n] @ pref (one mmul32) then stream y = P @ x0.
// Concurrency probe: NCHUNK=8 -> 4096 out-blocks (4 waves). Curve so far:
// 512blk=2.83, 1024=4.85, 2048=5.22 TB/s store throughput.

#define MAX_T   8192
#define SPB     128                 // slots per scan block
#define MAX_NB  (MAX_T / SPB)       // 64
#define NCHUNK  8                   // n-rows per out-block (4096 blocks)

__device__ float4   g_L[MAX_T];     // block-local inclusive products
__device__ float4   g_agg[MAX_NB];  // per-scan-block aggregates
__device__ float4   g_pref[MAX_NB]; // exclusive prefixes (g_pref[0] = I)
__device__ unsigned g_count;        // monotonic; (old+1) % gridDim.x == 0 -> last block

// fp32 2x2 multiply: R = X @ Y  (x=00 y=01 z=10 w=11)
__device__ __forceinline__ float4 mmul32(float4 X, float4 Y) {
    float4 r;
    r.x = X.x * Y.x + X.y * Y.z;
    r.y = X.x * Y.y + X.y * Y.w;
    r.z = X.z * Y.x + X.w * Y.z;
    r.w = X.z * Y.y + X.w * Y.w;
    return r;
}

struct M2d { double a, b, c, d; };
__device__ __forceinline__ M2d mmul64(const M2d& X, const M2d& Y) {
    M2d r;
    r.a = X.a * Y.a + X.b * Y.c;
    r.b = X.a * Y.b + X.b * Y.d;
    r.c = X.c * Y.a + X.d * Y.c;
    r.d = X.c * Y.b + X.d * Y.d;
    return r;
}
__device__ __forceinline__ M2d toD(float4 v) {
    return { (double)v.x, (double)v.y, (double)v.z, (double)v.w };
}
__device__ __forceinline__ float4 toF(const M2d& v) {
    return make_float4((float)v.a, (float)v.b, (float)v.c, (float)v.d);
}

__device__ __forceinline__ float4 shflup4(float4 v, int off) {
    float4 r;
    r.x = __shfl_up_sync(0xFFFFFFFFu, v.x, off);
    r.y = __shfl_up_sync(0xFFFFFFFFu, v.y, off);
    r.z = __shfl_up_sync(0xFFFFFFFFu, v.z, off);
    r.w = __shfl_up_sync(0xFFFFFFFFu, v.w, off);
    return r;
}
__device__ __forceinline__ M2d shflupD(const M2d& v, int off) {
    M2d r;
    r.a = __shfl_up_sync(0xFFFFFFFFu, v.a, off);
    r.b = __shfl_up_sync(0xFFFFFFFFu, v.b, off);
    r.c = __shfl_up_sync(0xFFFFFFFFu, v.c, off);
    r.d = __shfl_up_sync(0xFFFFFFFFu, v.d, off);
    return r;
}

// sin(x) for |x| up to ~1e3: Cody-Waite 2-term reduction + MUFU sin.
__device__ __forceinline__ float fast_sin(float x) {
    float k = rintf(x * 0.15915494309189535f);
    float r = fmaf(k, -6.2831855f, x);
    r = fmaf(k, 1.7484555e-7f, r);
    return __sinf(r);
}

// ---------------------------------------------------------------------------
// K1
// ---------------------------------------------------------------------------
__global__ void __launch_bounds__(SPB)
k1_E_scan(const float* __restrict__ t,
          const float* __restrict__ p_w,
          const float* __restrict__ p_g0,
          const float* __restrict__ p_ga,
          const float* __restrict__ p_wd,
          const int*   __restrict__ p_uc,
          int T)
{
    __shared__ float4 sWA[4], sWP[4];
    __shared__ int sLast;
    const int tid  = threadIdx.x;
    const int lane = tid & 31;
    const int wid  = tid >> 5;
    const int s    = blockIdx.x * SPB + tid;

    float4 E = make_float4(1.0f, 0.0f, 0.0f, 1.0f);
    if (s >= 1 && s < T) {
        const float w  = *p_w;
        const float g0 = *p_g0;
        const float ga = *p_ga;
        const float wd = *p_wd;
        const int   uc = *p_uc;

        const int i = s - 1;
        const float t0 = t[i];
        const float t1 = t[i + 1];
        const float dt = t1 - t0;
        const float tm = t0 + dt * 0.5f;
        const float gm = g0 * (1.0f + ga * fast_sin(wd * tm));

        float O00 = 0.0f;
        float O01 = dt;
        float O10 = -w * dt;
        float O11 = -gm * dt;
        if (uc) {
            const float gA = g0 * (1.0f + ga * fast_sin(wd * t0));
            const float gB = g0 * (1.0f + ga * fast_sin(wd * t1));
            const float dg = gA - gB;
            const float c  = dt * dt * (1.0f / 12.0f);
            O01 += c * dg;
            O10 += c * w * dg;
        }

        const float m     = 0.5f * (O00 + O11);
        const float det   = O00 * O11 - O01 * O10;
        const float delta = m * m - det;

        float cosl, sinch;
        if (fabsf(delta) < 0.01f) {
            cosl  = 1.0f + delta * (0.5f + delta * (1.0f / 24.0f));
            sinch = 1.0f + delta * ((1.0f / 6.0f) + delta * (1.0f / 120.0f));
        } else {
            const float sq    = sqrtf(fabsf(delta));
            const bool  pos   = (delta >= 0.0f);
            const bool  smll  = (sq < 1e-6f);
            const float ssafe = smll ? 1.0f : sq;
            cosl  = pos ? coshf(sq) : cosf(sq);
            sinch = smll ? 1.0f : ((pos ? sinhf(ssafe) : sinf(ssafe)) / ssafe);
        }
        const float em = __expf(m);

        E.x = em * (cosl + sinch * (O00 - m));
        E.y = em * (sinch * O01);
        E.z = em * (sinch * O10);
        E.w = em * (cosl + sinch * (O11 - m));
    }

    // warp-level inclusive scan (combine: newer @ older; adjacent segments)
    float4 agg = E;
    #pragma unroll
    for (int off = 1; off < 32; off <<= 1) {
        float4 prev = shflup4(agg, off);
        if (lane >= off) agg = mmul32(agg, prev);
    }
    if (lane == 31) sWA[wid] = agg;
    __syncthreads();
    if (tid == 0) {
        float4 p = make_float4(1.0f, 0.0f, 0.0f, 1.0f);
        #pragma unroll
        for (int wi = 0; wi < 4; wi++) { sWP[wi] = p; p = mmul32(sWA[wi], p); }
    }
    __syncthreads();
    if (wid > 0) agg = mmul32(agg, sWP[wid]);

    if (s < T) g_L[s] = agg;

    // publish aggregate; detect last-finishing block (monotonic, replay-safe)
    if (tid == SPB - 1) {
        g_agg[blockIdx.x] = agg;
        __threadfence();
        unsigned old = atomicAdd(&g_count, 1u);
        sLast = (((old + 1) % gridDim.x) == 0) ? 1 : 0;
    }
    __syncthreads();

    // last block: one-warp fp64 scan over NB aggregates -> exclusive prefixes
    if (sLast && wid == 0) {
        __threadfence();
        const int NB = gridDim.x;      // 64 for T=8192
        const int i0 = 2 * lane, i1 = 2 * lane + 1;
        const M2d I = {1.0, 0.0, 0.0, 1.0};
        M2d a0 = (i0 < NB) ? toD(g_agg[i0]) : I;
        M2d a1 = (i1 < NB) ? toD(g_agg[i1]) : I;
        M2d p  = mmul64(a1, a0);       // pair product, ordered newer@older
        #pragma unroll
        for (int off = 1; off < 32; off <<= 1) {
            M2d prev = shflupD(p, off);
            if (lane >= off) p = mmul64(p, prev);
        }
        M2d Sm1 = shflupD(p, 1);
        M2d pref0 = (lane == 0) ? I : Sm1;
        M2d pref1 = mmul64(a0, pref0);
        if (i0 < MAX_NB) g_pref[i0] = toF(pref0);
        if (i1 < MAX_NB) g_pref[i1] = toF(pref1);
    }
}

// ---------------------------------------------------------------------------
// K3: stage P for NCHUNK rows (one mmul32 fixup), then stream y = P @ x0.
// Proven loop shape: #pragma unroll 4, running pointer, per-iter guard.
// ---------------------------------------------------------------------------
__global__ void __launch_bounds__(256)
k3_out(const float* __restrict__ x0,
       float* __restrict__ out,
       int B, int T)
{
    __shared__ float4 sP[NCHUNK];
    const int tid = threadIdx.x;
    const int B4  = B >> 2;
    const int b4  = blockIdx.x * 256 + tid;
    const int n0  = blockIdx.y * NCHUNK;

    if (tid < NCHUNK) {
        int nn = n0 + tid;
        if (nn >= T) nn = T - 1;
        float4 L  = g_L[nn];
        float4 pr = g_pref[n0 >> 7];   // SPB == 128; constant over the chunk
        sP[tid] = mmul32(L, pr);       // g_pref[0] == I
    }
    __syncthreads();

    if (b4 >= B4) return;

    const float4 a0 = ((const float4*)x0)[b4];
    const float4 a1 = ((const float4*)(x0 + B))[b4];

    float4* o = (float4*)out + (size_t)n0 * 2 * B4 + b4;

    #pragma unroll 4
    for (int j = 0; j < NCHUNK; j++) {
        const int n = n0 + j;
        if (n >= T) break;
        const float4 P = sP[j];

        float4 y0, y1;
        y0.x = P.x * a0.x + P.y * a1.x;
        y0.y = P.x * a0.y + P.y * a1.y;
        y0.z = P.x * a0.z + P.y * a1.z;
        y0.w = P.x * a0.w + P.y * a1.w;
        y1.x = P.z * a0.x + P.w * a1.x;
        y1.y = P.z * a0.y + P.w * a1.y;
        y1.z = P.z * a0.z + P.w * a1.z;
        y1.w = P.z * a0.w + P.w * a1.w;

        __stcs(o, y0);
        __stcs(o + B4, y1);
        o += 2 * B4;
    }
}

// ---------------------------------------------------------------------------
extern "C" void kernel_launch(void* const* d_in, const int* in_sizes, int n_in,
                              void* d_out, int out_size)
{
    const float* t  = (const float*)d_in[0];
    const float* x0 = (const float*)d_in[1];
    const float* w  = (const float*)d_in[2];
    const float* g0 = (const float*)d_in[3];
    const float* ga = (const float*)d_in[4];
    const float* wd = (const float*)d_in[5];
    const int*   uc = (const int*)d_in[6];
    float* out = (float*)d_out;

    const int T = in_sizes[0];       // 8192
    const int B = in_sizes[1] / 2;   // 4096
    const int NB = (T + SPB - 1) / SPB;   // 64

    k1_E_scan<<<NB, SPB>>>(t, w, g0, ga, wd, uc, T);

    {
        const int B4 = B >> 2;
        dim3 grid((B4 + 255) / 256, (T + NCHUNK - 1) / NCHUNK);
        k3_out<<<grid, 256>>>(x0, out, B, T);
    }
}

// round 17
// speedup vs baseline: 1.2091x; 1.0450x over previous
#include <cuda_runtime.h>

// Magnus2: x_{n+1} = E_n x_n, 2x2 time-dependent, batch-independent E.
//   K1: compute E + block-local (128-slot) fp32 scan; last-finishing block
//       computes all 64 exclusive block prefixes (fp32 warp scan) -> g_pref
//   K3: stage P[n] = L[n] @ pref (one mmul32) then stream y = P @ x0.
// NCHUNK=8 (4096 out-blocks) = best measured total. fp32 aggregate scan:
// adds ~5e-7 relative error (64-long chain), well inside the 1e-3 budget.

#define MAX_T   8192
#define SPB     128                 // slots per scan block
#define MAX_NB  (MAX_T / SPB)       // 64
#define NCHUNK  8                   // n-rows per out-block (4096 blocks)

__device__ float4   g_L[MAX_T];     // block-local inclusive products
__device__ float4   g_agg[MAX_NB];  // per-scan-block aggregates
__device__ float4   g_pref[MAX_NB]; // exclusive prefixes (g_pref[0] = I)
__device__ unsigned g_count;        // monotonic; (old+1) % gridDim.x == 0 -> last block

// fp32 2x2 multiply: R = X @ Y  (x=00 y=01 z=10 w=11)
__device__ __forceinline__ float4 mmul32(float4 X, float4 Y) {
    float4 r;
    r.x = X.x * Y.x + X.y * Y.z;
    r.y = X.x * Y.y + X.y * Y.w;
    r.z = X.z * Y.x + X.w * Y.z;
    r.w = X.z * Y.y + X.w * Y.w;
    return r;
}

__device__ __forceinline__ float4 shflup4(float4 v, int off) {
    float4 r;
    r.x = __shfl_up_sync(0xFFFFFFFFu, v.x, off);
    r.y = __shfl_up_sync(0xFFFFFFFFu, v.y, off);
    r.z = __shfl_up_sync(0xFFFFFFFFu, v.z, off);
    r.w = __shfl_up_sync(0xFFFFFFFFu, v.w, off);
    return r;
}

// sin(x) for |x| up to ~1e3: Cody-Waite 2-term reduction + MUFU sin.
__device__ __forceinline__ float fast_sin(float x) {
    float k = rintf(x * 0.15915494309189535f);
    float r = fmaf(k, -6.2831855f, x);
    r = fmaf(k, 1.7484555e-7f, r);
    return __sinf(r);
}

// ---------------------------------------------------------------------------
// K1
// ---------------------------------------------------------------------------
__global__ void __launch_bounds__(SPB)
k1_E_scan(const float* __restrict__ t,
          const float* __restrict__ p_w,
          const float* __restrict__ p_g0,
          const float* __restrict__ p_ga,
          const float* __restrict__ p_wd,
          const int*   __restrict__ p_uc,
          int T)
{
    __shared__ float4 sWA[4], sWP[4];
    __shared__ int sLast;
    const int tid  = threadIdx.x;
    const int lane = tid & 31;
    const int wid  = tid >> 5;
    const int s    = blockIdx.x * SPB + tid;

    float4 E = make_float4(1.0f, 0.0f, 0.0f, 1.0f);
    if (s >= 1 && s < T) {
        const float w  = *p_w;
        const float g0 = *p_g0;
        const float ga = *p_ga;
        const float wd = *p_wd;
        const int   uc = *p_uc;

        const int i = s - 1;
        const float t0 = t[i];
        const float t1 = t[i + 1];
        const float dt = t1 - t0;
        const float tm = t0 + dt * 0.5f;
        const float gm = g0 * (1.0f + ga * fast_sin(wd * tm));

        float O00 = 0.0f;
        float O01 = dt;
        float O10 = -w * dt;
        float O11 = -gm * dt;
        if (uc) {
            const float gA = g0 * (1.0f + ga * fast_sin(wd * t0));
            const float gB = g0 * (1.0f + ga * fast_sin(wd * t1));
            const float dg = gA - gB;
            const float c  = dt * dt * (1.0f / 12.0f);
            O01 += c * dg;
            O10 += c * w * dg;
        }

        const float m     = 0.5f * (O00 + O11);
        const float det   = O00 * O11 - O01 * O10;
        const float delta = m * m - det;

        float cosl, sinch;
        if (fabsf(delta) < 0.01f) {
            cosl  = 1.0f + delta * (0.5f + delta * (1.0f / 24.0f));
            sinch = 1.0f + delta * ((1.0f / 6.0f) + delta * (1.0f / 120.0f));
        } else {
            const float sq    = sqrtf(fabsf(delta));
            const bool  pos   = (delta >= 0.0f);
            const bool  smll  = (sq < 1e-6f);
            const float ssafe = smll ? 1.0f : sq;
            cosl  = pos ? coshf(sq) : cosf(sq);
            sinch = smll ? 1.0f : ((pos ? sinhf(ssafe) : sinf(ssafe)) / ssafe);
        }
        const float em = __expf(m);

        E.x = em * (cosl + sinch * (O00 - m));
        E.y = em * (sinch * O01);
        E.z = em * (sinch * O10);
        E.w = em * (cosl + sinch * (O11 - m));
    }

    // warp-level inclusive scan (combine: newer @ older; adjacent segments)
    float4 agg = E;
    #pragma unroll
    for (int off = 1; off < 32; off <<= 1) {
        float4 prev = shflup4(agg, off);
        if (lane >= off) agg = mmul32(agg, prev);
    }
    if (lane == 31) sWA[wid] = agg;
    __syncthreads();
    if (tid == 0) {
        float4 p = make_float4(1.0f, 0.0f, 0.0f, 1.0f);
        #pragma unroll
        for (int wi = 0; wi < 4; wi++) { sWP[wi] = p; p = mmul32(sWA[wi], p); }
    }
    __syncthreads();
    if (wid > 0) agg = mmul32(agg, sWP[wid]);

    if (s < T) g_L[s] = agg;

    // publish aggregate; detect last-finishing block (monotonic, replay-safe)
    if (tid == SPB - 1) {
        g_agg[blockIdx.x] = agg;
        __threadfence();
        unsigned old = atomicAdd(&g_count, 1u);
        sLast = (((old + 1) % gridDim.x) == 0) ? 1 : 0;
    }
    __syncthreads();

    // last block: one-warp fp32 scan over NB aggregates -> exclusive prefixes
    if (sLast && wid == 0) {
        __threadfence();
        const int NB = gridDim.x;      // 64 for T=8192
        const int i0 = 2 * lane, i1 = 2 * lane + 1;
        const float4 I = make_float4(1.0f, 0.0f, 0.0f, 1.0f);
        float4 a0 = (i0 < NB) ? g_agg[i0] : I;
        float4 a1 = (i1 < NB) ? g_agg[i1] : I;
        float4 p  = mmul32(a1, a0);    // pair product, ordered newer@older
        #pragma unroll
        for (int off = 1; off < 32; off <<= 1) {
            float4 prev = shflup4(p, off);
            if (lane >= off) p = mmul32(p, prev);
        }
        float4 Sm1 = shflup4(p, 1);    // inclusive up to pair lane-1
        float4 pref0 = (lane == 0) ? I : Sm1;     // exclusive prefix of block i0
        float4 pref1 = mmul32(a0, pref0);          // exclusive prefix of block i1
        if (i0 < MAX_NB) g_pref[i0] = pref0;
        if (i1 < MAX_NB) g_pref[i1] = pref1;
    }
}

// ---------------------------------------------------------------------------
// K3: stage P for NCHUNK rows (one mmul32 fixup), then stream y = P @ x0.
// Proven loop shape: #pragma unroll 4, running pointer, per-iter guard.
// ---------------------------------------------------------------------------
__global__ void __launch_bounds__(256)
k3_out(const float* __restrict__ x0,
       float* __restrict__ out,
       int B, int T)
{
    __shared__ float4 sP[NCHUNK];
    const int tid = threadIdx.x;
    const int B4  = B >> 2;
    const int b4  = blockIdx.x * 256 + tid;
    const int n0  = blockIdx.y * NCHUNK;

    if (tid < NCHUNK) {
        int nn = n0 + tid;
        if (nn >= T) nn = T - 1;
        float4 L  = g_L[nn];
        float4 pr = g_pref[n0 >> 7];   // SPB == 128; constant over the chunk
        sP[tid] = mmul32(L, pr);       // g_pref[0] == I
    }
    __syncthreads();

    if (b4 >= B4) return;

    const float4 a0 = ((const float4*)x0)[b4];
    const float4 a1 = ((const float4*)(x0 + B))[b4];

    float4* o = (float4*)out + (size_t)n0 * 2 * B4 + b4;

    #pragma unroll 4
    for (int j = 0; j < NCHUNK; j++) {
        const int n = n0 + j;
        if (n >= T) break;
        const float4 P = sP[j];

        float4 y0, y1;
        y0.x = P.x * a0.x + P.y * a1.x;
        y0.y = P.x * a0.y + P.y * a1.y;
        y0.z = P.x * a0.z + P.y * a1.z;
        y0.w = P.x * a0.w + P.y * a1.w;
        y1.x = P.z * a0.x + P.w * a1.x;
        y1.y = P.z * a0.y + P.w * a1.y;
        y1.z = P.z * a0.z + P.w * a1.z;
        y1.w = P.z * a0.w + P.w * a1.w;

        __stcs(o, y0);
        __stcs(o + B4, y1);
        o += 2 * B4;
    }
}

// ---------------------------------------------------------------------------
extern "C" void kernel_launch(void* const* d_in, const int* in_sizes, int n_in,
                              void* d_out, int out_size)
{
    const float* t  = (const float*)d_in[0];
    const float* x0 = (const float*)d_in[1];
    const float* w  = (const float*)d_in[2];
    const float* g0 = (const float*)d_in[3];
    const float* ga = (const float*)d_in[4];
    const float* wd = (const float*)d_in[5];
    const int*   uc = (const int*)d_in[6];
    float* out = (float*)d_out;

    const int T = in_sizes[0];       // 8192
    const int B = in_sizes[1] / 2;   // 4096
    const int NB = (T + SPB - 1) / SPB;   // 64

    k1_E_scan<<<NB, SPB>>>(t, w, g0, ga, wd, uc, T);

    {
        const int B4 = B >> 2;
        dim3 grid((B4 + 255) / 256, (T + NCHUNK - 1) / NCHUNK);
        k3_out<<<grid, 256>>>(x0, out, B, T);
    }
}